// round 10
// baseline (speedup 1.0000x reference)
#include <cuda_runtime.h>
#include <cuda_bf16.h>
#include <math.h>
#include <cstdint>

// Problem constants
#define Bn 4
#define Tn 256
#define Un 64
#define U1 65
#define Vn 1024
#define Fn 80
#define Hn 512
#define Jn 512
#define NROWS (Bn*Tn*U1)   // 66560 = 520*128
#define NEGF (-1e30f)

// ---------------- scratch (static __device__, allocation-free) ----------------
__device__ float g_Wcomb[Fn*Jn];                 // W_enc @ W_jenc (80x512)
__device__ float g_e  [Bn*Tn*Jn];                // (1024, 512)
__device__ float g_dec[Bn*U1*Hn];                // (260, 512)
__device__ float g_d  [Bn*U1*Jn];                // (260, 512)
__device__ uint8_t g_Wt8[(size_t)Vn*Jn];         // e4m3(16*W_out^T), [V][J] K-major
__device__ float g_blank[NROWS];
__device__ float g_lbl[Bn*Tn*Un];

__device__ __forceinline__ float lae(float a, float b){
    float m = fmaxf(a,b);
    return m + log1pf(__expf(fminf(a,b) - m));
}
__device__ __forceinline__ uint32_t s2u(const void* p){
    uint32_t a;
    asm("{ .reg .u64 t; cvta.to.shared.u64 t, %1; cvt.u32.u64 %0, t; }" : "=r"(a) : "l"(p));
    return a;
}
__device__ __forceinline__ float tanhap(float x){
    float y; asm("tanh.approx.f32 %0, %1;" : "=f"(y) : "f"(x)); return y;
}
// per-row swizzle bits for 64B rows: flips 16B-chunk index (bits 4,5) by row bits 1,2
#define XBITS(r) ((((uint32_t)(r))&6u)<<3)

// ---------------- small tiled SGEMM: C(M,N) = A(M,K) @ B(K,N), 32x32 tiles ----------------
__global__ void gemm32(const float* __restrict__ A, const float* __restrict__ B,
                       float* __restrict__ C, int M, int N, int K){
    __shared__ float As[32][33];
    __shared__ float Bs[32][33];
    int tid = threadIdx.x;
    int tx = tid & 15, ty = tid >> 4;
    int rowBase = blockIdx.y*32, colBase = blockIdx.x*32;
    float acc[2][2] = {};
    for(int k0=0;k0<K;k0+=32){
        #pragma unroll
        for(int i=0;i<4;i++){
            int idx = i*256+tid;
            int m = idx>>5, k = idx&31;
            int gm = rowBase+m, gk = k0+k;
            As[m][k] = (gm<M && gk<K) ? A[(size_t)gm*K+gk] : 0.f;
            int kb = idx>>5, n = idx&31;
            int gkb = k0+kb, gn = colBase+n;
            Bs[kb][n] = (gkb<K && gn<N) ? B[(size_t)gkb*N+gn] : 0.f;
        }
        __syncthreads();
        #pragma unroll
        for(int kk=0;kk<32;kk++){
            float a0 = As[ty*2+0][kk], a1 = As[ty*2+1][kk];
            float b0 = Bs[kk][tx*2+0], b1 = Bs[kk][tx*2+1];
            acc[0][0] = fmaf(a0,b0,acc[0][0]);
            acc[0][1] = fmaf(a0,b1,acc[0][1]);
            acc[1][0] = fmaf(a1,b0,acc[1][0]);
            acc[1][1] = fmaf(a1,b1,acc[1][1]);
        }
        __syncthreads();
    }
    #pragma unroll
    for(int i=0;i<2;i++){
        int gm = rowBase+ty*2+i;
        if(gm<M)
            #pragma unroll
            for(int j=0;j<2;j++){
                int gn = colBase+tx*2+j;
                if(gn<N) C[(size_t)gm*N+gn]=acc[i][j];
            }
    }
}

// ---------------- gather decoder embedding rows ----------------
__global__ void gather_dec(const float* __restrict__ emb, const int* __restrict__ targets){
    int row = blockIdx.x;            // 0..259 = b*65+u
    int b = row / U1, u = row - b*U1;
    int tok = (u==0) ? 0 : targets[b*Un + (u-1)];
    const float* src = emb + (size_t)tok*Hn;
    float* dst = g_dec + (size_t)row*Hn;
    for(int k=threadIdx.x;k<Hn;k+=blockDim.x) dst[k]=src[k];
}

// ---------------- transpose W_out (J,V) fp32 -> g_Wt8 (V,J) e4m3 scaled x16 ----------------
__global__ void wtrans8(const float* __restrict__ W){
    __shared__ float t[32][33];
    int v0 = blockIdx.x*32, j0 = blockIdx.y*32;
    for(int i=threadIdx.y;i<32;i+=8)
        t[i][threadIdx.x] = W[(size_t)(j0+i)*Vn + v0 + threadIdx.x];
    __syncthreads();
    for(int i=threadIdx.y;i<32;i+=8){
        if(threadIdx.x < 16){
            float a = t[threadIdx.x*2  ][i]*16.f;   // j = j0+2tx   (lower byte)
            float b = t[threadIdx.x*2+1][i]*16.f;   // j = j0+2tx+1 (upper byte)
            uint16_t p;
            asm("cvt.rn.satfinite.e4m3x2.f32 %0, %1, %2;" : "=h"(p) : "f"(b), "f"(a));
            *(uint16_t*)(g_Wt8 + (size_t)(v0+i)*Jn + j0 + threadIdx.x*2) = p;
        }
    }
}

// ================= fused joint kernel (FP8 e4m3 mma) =================
// 520 CTAs x 256 threads (8 warps, 4m x 2n). Each CTA: 128 rows x 1024 cols.
// A full-K e4m3(8*h) [8 kt][128 rows][64B swizzled] = 64KB; B 6-stage ring 6x8KB = 48KB.
// Swizzle: addr = base + row*64 + (off ^ XBITS(row)). 64 steps, 2 per barrier.
// acc = 128 * true logit (h*8, w*16) -> epilogue scales by 1/128.
#define ABYTES (8*128*64)             // 65536
#define BRING  (6*128*64)             // 49152
#define BIG_SMEM (ABYTES + BRING)     // 114688 -> 2 CTAs/SM
__global__ void __launch_bounds__(256) big_fused(const float* __restrict__ bout,
                                                 const float* __restrict__ bj,
                                                 const int* __restrict__ targets,
                                                 const int* __restrict__ tgt_lens){
    extern __shared__ char sm[];
    uint32_t sA = s2u(sm);
    uint32_t sB = sA + ABYTES;
    // stats overlay on B ring (only written after mainloop reads of those bufs)
    float* pm  = (float*)(sm + ABYTES);         // [2][128]
    float* ps  = pm + 256;                      // [2][128]
    float* pvt = ps + 256;                      // [2][128]
    float* pv0 = pvt + 256;                     // [128]

    int tid = threadIdx.x, wid = tid>>5, lane = tid&31;
    int g = lane>>2, tg = lane&3;
    int warp_m = wid & 3, warp_n = wid >> 2;    // 4 x 2
    int rowBase = blockIdx.x*128;

    // ---- prologue: e4m3(8*tanh(e+d+bj)) into A smem; warp owns 16 rows ----
    {
        int r0 = wid*16;
        #pragma unroll
        for(int rr=0;rr<16;rr++){
            int r = r0 + rr;
            int row = rowBase + r;
            int bt = row / U1, u = row - bt*U1, b = bt >> 8;
            const float4* ep = (const float4*)(g_e + (size_t)bt*Jn);
            const float4* dp = (const float4*)(g_d + (size_t)(b*U1+u)*Jn);
            const float4* bp = (const float4*)bj;
            uint32_t xr = XBITS(r);
            uint32_t colsw = (((uint32_t)(lane&15))*4u) ^ xr;  // byte in 64B row
            #pragma unroll
            for(int i=0;i<4;i++){
                int k = i*128 + lane*4;
                float4 e4 = ep[k>>2], d4 = dp[k>>2], b4 = bp[k>>2];
                float y0 = tanhap(e4.x+d4.x+b4.x)*8.f;
                float y1 = tanhap(e4.y+d4.y+b4.y)*8.f;
                float y2 = tanhap(e4.z+d4.z+b4.z)*8.f;
                float y3 = tanhap(e4.w+d4.w+b4.w)*8.f;
                uint16_t lo16, hi16;
                asm("cvt.rn.satfinite.e4m3x2.f32 %0, %1, %2;" : "=h"(lo16) : "f"(y1), "f"(y0));
                asm("cvt.rn.satfinite.e4m3x2.f32 %0, %1, %2;" : "=h"(hi16) : "f"(y3), "f"(y2));
                uint32_t wv = (uint32_t)lo16 | ((uint32_t)hi16 << 16);
                int kt = i*2 + (lane>>4);                       // k/64
                uint32_t addr = sA + (uint32_t)kt*8192 + (uint32_t)r*64 + colsw;
                asm volatile("st.shared.b32 [%0], %1;" :: "r"(addr), "r"(wv));
            }
        }
    }

    // per-slot row info (slot = mt*2 + half)
    int rows4[4], tgt4[4];
    #pragma unroll
    for(int mt=0;mt<2;mt++)
        #pragma unroll
        for(int half=0;half<2;half++){
            int s = mt*2+half;
            int rl = warp_m*32 + mt*16 + half*8 + g;
            rows4[s] = rl;
            int row = rowBase + rl;
            int bt = row / U1, u = row - bt*U1, b = bt >> 8;
            tgt4[s] = (u < Un) ? targets[b*Un + u] : -1;
        }

    // ldmatrix swizzled offsets within a kt/buffer tile, both ks (k32 halves)
    uint32_t aOff2[2][2];
    #pragma unroll
    for(int mt=0;mt<2;mt++){
        int r = warp_m*32 + mt*16 + (lane&7) + ((lane>>3)&1)*8;
        uint32_t off16 = ((lane>>4)&1)*16;
        #pragma unroll
        for(int ks=0;ks<2;ks++)
            aOff2[mt][ks] = (uint32_t)r*64 + ((off16 | (ks<<5)) ^ XBITS(r));
    }
    uint32_t bOff2[4][2];
    #pragma unroll
    for(int j=0;j<4;j++){
        int n = warp_n*64 + j*16 + (lane&7) + ((lane>>4)&1)*8;
        uint32_t off16 = ((lane>>3)&1)*16;
        #pragma unroll
        for(int ks=0;ks<2;ks++)
            bOff2[j][ks] = (uint32_t)n*64 + ((off16 | (ks<<5)) ^ XBITS(n));
    }

    float m4[4] = {-3.4e38f,-3.4e38f,-3.4e38f,-3.4e38f};
    float s4[4] = {0.f,0.f,0.f,0.f};
    float vt4[4] = {-3.4e38f,-3.4e38f,-3.4e38f,-3.4e38f};
    float v04[4] = {0.f,0.f,0.f,0.f};

    int brow = tid>>1, bc0 = (tid&1)*2;   // 128 n-rows x 2 x 16B per thread per kt
    uint32_t bst0 = (uint32_t)brow*64 + (((uint32_t)bc0*16u)       ^ XBITS(brow));
    uint32_t bst1 = (uint32_t)brow*64 + (((uint32_t)bc0*16u + 16u) ^ XBITS(brow));
    #define LOADB(buf, stp) do{ \
        unsigned long long p = __cvta_generic_to_global( \
            (const char*)g_Wt8 + ((size_t)(((stp)>>3)*128 + brow))*512 + ((stp)&7)*64 + bc0*16); \
        uint32_t dbase = sB + (uint32_t)(buf)*8192; \
        asm volatile("cp.async.cg.shared.global [%0], [%1], 16;" :: "r"(dbase + bst0), "l"(p)); \
        asm volatile("cp.async.cg.shared.global [%0], [%1], 16;" :: "r"(dbase + bst1), "l"(p+16)); \
    }while(0)

    // prologue prefetch: steps 0..3 (one commit group each)
    LOADB(0,0); asm volatile("cp.async.commit_group;");
    LOADB(1,1); asm volatile("cp.async.commit_group;");
    LOADB(2,2); asm volatile("cp.async.commit_group;");
    LOADB(3,3); asm volatile("cp.async.commit_group;");

    float acc[2][8][4];
    #pragma unroll
    for(int mt=0;mt<2;mt++)
        #pragma unroll
        for(int nt=0;nt<8;nt++)
            #pragma unroll
            for(int c=0;c<4;c++) acc[mt][nt][c]=0.f;

    for(int it=0; it<32; it++){
        int p0 = 2*it;
        // wait: pending groups = {p0+2,p0+3} + just-issued later; here pending = 4, keep 2
        asm volatile("cp.async.wait_group 2;");
        __syncthreads();
        // issue prefetch AFTER sync: ring slot (p0+4)%6 == (p0-2)%6 was read last iter
        if(p0+4 < 64){ LOADB((p0+4)%6, p0+4); }
        asm volatile("cp.async.commit_group;");
        if(p0+5 < 64){ LOADB((p0+5)%6, p0+5); }
        asm volatile("cp.async.commit_group;");

        #pragma unroll
        for(int half2=0; half2<2; half2++){
            int stp = p0 + half2;
            uint32_t aoff = sA + (uint32_t)(stp & 7)*8192;
            uint32_t boff = sB + (uint32_t)(stp % 6)*8192;
            #pragma unroll
            for(int ks=0;ks<2;ks++){
                uint32_t af[2][4];
                #pragma unroll
                for(int mt=0;mt<2;mt++)
                    asm volatile("ldmatrix.sync.aligned.m8n8.x4.shared.b16 {%0,%1,%2,%3}, [%4];"
                        : "=r"(af[mt][0]),"=r"(af[mt][1]),"=r"(af[mt][2]),"=r"(af[mt][3])
                        : "r"(aoff + aOff2[mt][ks]));
                uint32_t bf[8][2];
                #pragma unroll
                for(int j=0;j<4;j++){
                    uint32_t b0,b1,b2,b3;
                    asm volatile("ldmatrix.sync.aligned.m8n8.x4.shared.b16 {%0,%1,%2,%3}, [%4];"
                        : "=r"(b0),"=r"(b1),"=r"(b2),"=r"(b3)
                        : "r"(boff + bOff2[j][ks]));
                    bf[2*j][0]=b0; bf[2*j][1]=b1; bf[2*j+1][0]=b2; bf[2*j+1][1]=b3;
                }
                #pragma unroll
                for(int mt=0;mt<2;mt++)
                    #pragma unroll
                    for(int nt=0;nt<8;nt++)
                        asm volatile(
                            "mma.sync.aligned.m16n8k32.row.col.f32.e4m3.e4m3.f32 "
                            "{%0,%1,%2,%3}, {%4,%5,%6,%7}, {%8,%9}, {%0,%1,%2,%3};"
                            : "+f"(acc[mt][nt][0]), "+f"(acc[mt][nt][1]),
                              "+f"(acc[mt][nt][2]), "+f"(acc[mt][nt][3])
                            : "r"(af[mt][0]),"r"(af[mt][1]),"r"(af[mt][2]),"r"(af[mt][3]),
                              "r"(bf[nt][0]),"r"(bf[nt][1]));
            }
        }

        if(((p0+1) & 7) == 7){
            int nch = (p0+1) >> 3;
            // ---- chunk epilogue: running softmax stats over these 128 cols ----
            const float sc = 0.0078125f;   // 1/128 undoes h*8, w*16
            int colw = nch*128 + warp_n*64;
            float br0[8], br1[8];
            #pragma unroll
            for(int nt=0;nt<8;nt++){
                br0[nt] = __ldg(&bout[colw + nt*8 + tg*2]);
                br1[nt] = __ldg(&bout[colw + nt*8 + tg*2 + 1]);
            }
            #pragma unroll
            for(int mt=0;mt<2;mt++){
                #pragma unroll
                for(int half=0;half<2;half++){
                    int slot = mt*2+half;
                    float v[16];
                    float cm = -3.4e38f;
                    #pragma unroll
                    for(int nt=0;nt<8;nt++){
                        v[nt*2]   = acc[mt][nt][half*2]  *sc + br0[nt];
                        v[nt*2+1] = acc[mt][nt][half*2+1]*sc + br1[nt];
                        cm = fmaxf(cm, fmaxf(v[nt*2], v[nt*2+1]));
                    }
                    float nm = fmaxf(m4[slot], cm);
                    float s = s4[slot]*__expf(m4[slot]-nm);
                    #pragma unroll
                    for(int nt=0;nt<8;nt++){
                        s += __expf(v[nt*2]-nm);
                        s += __expf(v[nt*2+1]-nm);
                        int c0 = colw + nt*8 + tg*2;
                        if(c0   == tgt4[slot]) vt4[slot] = v[nt*2];
                        if(c0+1 == tgt4[slot]) vt4[slot] = v[nt*2+1];
                    }
                    m4[slot] = nm; s4[slot] = s;
                    if(nch==0 && warp_n==0 && tg==0) v04[slot] = v[0];
                }
            }
            // reset accumulators for next chunk
            #pragma unroll
            for(int mt=0;mt<2;mt++)
                #pragma unroll
                for(int nt=0;nt<8;nt++)
                    #pragma unroll
                    for(int c=0;c<4;c++) acc[mt][nt][c]=0.f;
        }
    }
    #undef LOADB

    // ---- cross-quad + cross-warp_n combine ----
    #pragma unroll
    for(int slot=0;slot<4;slot++){
        #pragma unroll
        for(int o=1;o<4;o<<=1){
            float om = __shfl_xor_sync(0xffffffffu, m4[slot], o);
            float os = __shfl_xor_sync(0xffffffffu, s4[slot], o);
            float ov = __shfl_xor_sync(0xffffffffu, vt4[slot], o);
            float nm = fmaxf(m4[slot], om);
            s4[slot] = s4[slot]*__expf(m4[slot]-nm) + os*__expf(om-nm);
            m4[slot] = nm;
            vt4[slot] = fmaxf(vt4[slot], ov);
        }
        if(tg==0){
            int rl = rows4[slot];
            pm [warp_n*128 + rl] = m4[slot];
            ps [warp_n*128 + rl] = s4[slot];
            pvt[warp_n*128 + rl] = vt4[slot];
            if(warp_n==0) pv0[rl] = v04[slot];
        }
    }
    __syncthreads();
    if(tid < 128){
        int r = tid;
        int row = rowBase + r;
        float m0 = pm[r], m1 = pm[128+r];
        float nm = fmaxf(m0, m1);
        float s = ps[r]*__expf(m0-nm) + ps[128+r]*__expf(m1-nm);
        float lse = nm + logf(s);
        g_blank[row] = pv0[r] - lse;
        int bt = row / U1, u = row - bt*U1;
        if(u < Un){
            int b = bt >> 8;
            float vt = fmaxf(pvt[r], pvt[128+r]);
            g_lbl[bt*Un+u] = (u < tgt_lens[b]) ? (vt - lse) : NEGF;
        }
    }
}

__global__ void zero_out(float* out){ if(threadIdx.x==0) out[0]=0.f; }

// ---------------- RNN-T forward DP: wavefront over SMEM-resident tables ----------------
#define DP_SMEM ((Tn*U1 + Tn*Un)*4)   // 132096 bytes
__global__ void dp_kernel(const int* __restrict__ in_lens, const int* __restrict__ tgt_lens,
                          float* __restrict__ out){
    extern __shared__ float smf[];
    float* s_blank = smf;              // Tn*U1
    float* s_lbl   = smf + Tn*U1;      // Tn*Un
    int b = blockIdx.x;
    for(int i=threadIdx.x;i<Tn*U1;i+=blockDim.x) s_blank[i] = g_blank[b*Tn*U1 + i];
    for(int i=threadIdx.x;i<Tn*Un;i+=blockDim.x) s_lbl[i]   = g_lbl[b*Tn*Un + i];
    __shared__ float buf[2][U1];
    __shared__ float fin;
    __syncthreads();
    int u = threadIdx.x;
    int tl = in_lens[b]-1;
    int uf = tgt_lens[b];
    int lim = tl + uf;
    for(int n=0;n<=lim;n++){
        float* cur = buf[n&1];
        const float* prev = buf[(n&1)^1];
        if(u <= Un){
            int t = n - u;
            if(t >= 0 && t < Tn){
                float val;
                if(t==0 && u==0)      val = 0.f;
                else if(t==0)         val = prev[u-1] + s_lbl[u-1];
                else if(u==0)         val = prev[0]   + s_blank[(t-1)*U1];
                else                  val = lae(prev[u]   + s_blank[(t-1)*U1 + u],
                                               prev[u-1] + s_lbl[t*Un + (u-1)]);
                cur[u] = val;
                if(t==tl && u==uf) fin = val + s_blank[t*U1 + u];
            }
        }
        __syncthreads();
    }
    if(threadIdx.x==0) atomicAdd(out, -fin * (1.0f/Bn));
}

// ---------------- launch ----------------
extern "C" void kernel_launch(void* const* d_in, const int* in_sizes, int n_in,
                              void* d_out, int out_size){
    (void)in_sizes; (void)n_in; (void)out_size;
    const float* inputs  = (const float*)d_in[0];
    const float* W_enc   = (const float*)d_in[1];
    const float* emb     = (const float*)d_in[2];
    const float* W_jenc  = (const float*)d_in[3];
    const float* W_jdec  = (const float*)d_in[4];
    const float* b_j     = (const float*)d_in[5];
    const float* W_out   = (const float*)d_in[6];
    const float* b_out   = (const float*)d_in[7];
    const int*   targets = (const int*)d_in[8];
    const int*   in_lens = (const int*)d_in[9];
    const int*   tgt_lens= (const int*)d_in[10];
    float* out = (float*)d_out;

    cudaFuncSetAttribute(big_fused, cudaFuncAttributeMaxDynamicSharedMemorySize, BIG_SMEM);
    cudaFuncSetAttribute(dp_kernel, cudaFuncAttributeMaxDynamicSharedMemorySize, DP_SMEM);

    void *p_wc, *p_e, *p_dec, *p_d;
    cudaGetSymbolAddress(&p_wc,  g_Wcomb);
    cudaGetSymbolAddress(&p_e,   g_e);
    cudaGetSymbolAddress(&p_dec, g_dec);
    cudaGetSymbolAddress(&p_d,   g_d);

    // W_comb = W_enc(80,512) @ W_jenc(512,512)
    gemm32<<<dim3(Jn/32, (Fn+31)/32), 256>>>(W_enc, W_jenc, (float*)p_wc, Fn, Jn, Hn);
    gather_dec<<<Bn*U1, 128>>>(emb, targets);
    wtrans8<<<dim3(Vn/32, Jn/32), dim3(32,8)>>>(W_out);
    // e = inputs(1024,80) @ W_comb(80,512)
    gemm32<<<dim3(Jn/32, (Bn*Tn)/32), 256>>>(inputs, (const float*)p_wc, (float*)p_e, Bn*Tn, Jn, Fn);
    // d = dec(260,512) @ W_jdec(512,512)
    gemm32<<<dim3(Jn/32, (Bn*U1+31)/32), 256>>>((const float*)p_dec, W_jdec, (float*)p_d, Bn*U1, Jn, Hn);
    big_fused<<<NROWS/128, 256, BIG_SMEM>>>(b_out, b_j, targets, tgt_lens);
    zero_out<<<1, 32>>>(out);
    dp_kernel<<<Bn, 128, DP_SMEM>>>(in_lens, tgt_lens, out);
}

// round 11
// speedup vs baseline: 1.2160x; 1.2160x over previous
#include <cuda_runtime.h>
#include <cuda_bf16.h>
#include <math.h>
#include <cstdint>

// Problem constants
#define Bn 4
#define Tn 256
#define Un 64
#define U1 65
#define Vn 1024
#define Fn 80
#define Hn 512
#define Jn 512
#define NROWS (Bn*Tn*U1)   // 66560 = 520*128
#define NEGF (-1e30f)

// ---------------- scratch (static __device__, allocation-free) ----------------
__device__ float g_Wcomb[Fn*Jn];                 // W_enc @ W_jenc (80x512)
__device__ float g_e  [Bn*Tn*Jn];                // (1024, 512)
__device__ float g_dec[Bn*U1*Hn];                // (260, 512)
__device__ float g_d  [Bn*U1*Jn];                // (260, 512)
__device__ __nv_bfloat16 g_Wt[(size_t)Vn*Jn];    // W_out^T bf16, [V][J] K-major
__device__ float g_blank[NROWS];                 // [b][t][u]
__device__ float g_lbl[Bn*Tn*Un];                // [b][t][u]

__device__ __forceinline__ float lae(float a, float b){
    float m = fmaxf(a,b);
    return m + log1pf(__expf(fminf(a,b) - m));
}
__device__ __forceinline__ uint32_t s2u(const void* p){
    uint32_t a;
    asm("{ .reg .u64 t; cvta.to.shared.u64 t, %1; cvt.u32.u64 %0, t; }" : "=r"(a) : "l"(p));
    return a;
}
__device__ __forceinline__ float tanhap(float x){
    float y; asm("tanh.approx.f32 %0, %1;" : "=f"(y) : "f"(x)); return y;
}
// per-row swizzle bits for 64B rows: flips 16B-chunk index (bits 4,5) by row bits 1,2
#define XBITS(r) ((((uint32_t)(r))&6u)<<3)

// ---------------- small tiled SGEMM: C(M,N) = A(M,K) @ B(K,N), 32x32 tiles ----------------
__global__ void gemm32(const float* __restrict__ A, const float* __restrict__ B,
                       float* __restrict__ C, int M, int N, int K){
    __shared__ float As[32][33];
    __shared__ float Bs[32][33];
    int tid = threadIdx.x;
    int tx = tid & 15, ty = tid >> 4;
    int rowBase = blockIdx.y*32, colBase = blockIdx.x*32;
    float acc[2][2] = {};
    for(int k0=0;k0<K;k0+=32){
        #pragma unroll
        for(int i=0;i<4;i++){
            int idx = i*256+tid;
            int m = idx>>5, k = idx&31;
            int gm = rowBase+m, gk = k0+k;
            As[m][k] = (gm<M && gk<K) ? A[(size_t)gm*K+gk] : 0.f;
            int kb = idx>>5, n = idx&31;
            int gkb = k0+kb, gn = colBase+n;
            Bs[kb][n] = (gkb<K && gn<N) ? B[(size_t)gkb*N+gn] : 0.f;
        }
        __syncthreads();
        #pragma unroll
        for(int kk=0;kk<32;kk++){
            float a0 = As[ty*2+0][kk], a1 = As[ty*2+1][kk];
            float b0 = Bs[kk][tx*2+0], b1 = Bs[kk][tx*2+1];
            acc[0][0] = fmaf(a0,b0,acc[0][0]);
            acc[0][1] = fmaf(a0,b1,acc[0][1]);
            acc[1][0] = fmaf(a1,b0,acc[1][0]);
            acc[1][1] = fmaf(a1,b1,acc[1][1]);
        }
        __syncthreads();
    }
    #pragma unroll
    for(int i=0;i<2;i++){
        int gm = rowBase+ty*2+i;
        if(gm<M)
            #pragma unroll
            for(int j=0;j<2;j++){
                int gn = colBase+tx*2+j;
                if(gn<N) C[(size_t)gm*N+gn]=acc[i][j];
            }
    }
}

// ---------------- gather decoder embedding rows (+ zero the output scalar) ----------------
__global__ void gather_dec(const float* __restrict__ emb, const int* __restrict__ targets,
                           float* __restrict__ out){
    if(blockIdx.x==0 && threadIdx.x==0) out[0] = 0.f;
    int row = blockIdx.x;            // 0..259 = b*65+u
    int b = row / U1, u = row - b*U1;
    int tok = (u==0) ? 0 : targets[b*Un + (u-1)];
    const float* src = emb + (size_t)tok*Hn;
    float* dst = g_dec + (size_t)row*Hn;
    for(int k=threadIdx.x;k<Hn;k+=blockDim.x) dst[k]=src[k];
}

// ---------------- transpose W_out (J,V) fp32 -> g_Wt (V,J) bf16 ----------------
__global__ void wtrans(const float* __restrict__ W){
    __shared__ float t[32][33];
    int v0 = blockIdx.x*32, j0 = blockIdx.y*32;
    for(int i=threadIdx.y;i<32;i+=8)
        t[i][threadIdx.x] = W[(size_t)(j0+i)*Vn + v0 + threadIdx.x];
    __syncthreads();
    for(int i=threadIdx.y;i<32;i+=8)
        g_Wt[(size_t)(v0+i)*Jn + j0 + threadIdx.x] = __float2bfloat16(t[threadIdx.x][i]);
}

// ================= fused joint kernel (u-major tiling + dead-CTA skip) =================
// Grid 520 = 65 u x 4 b x 2 t-halves. CTA: 128 t-rows (single u,b) x 1024 cols.
// Early exit if u > tgt_lens[b] or t0 >= in_lens[b]  (rows never read by DP).
// A full-K [16 kt][128 rows][64B swizzled] = 128KB; B 8-stage ring 8x8KB = 64KB.
// Swizzle: addr = base + row*64 + (off ^ XBITS(row)). 2 kt per barrier, dist 4.
#define ABYTES (16*128*64)            // 131072
#define BRING  (8*128*64)             // 65536
#define SOFFB  (ABYTES + BRING)       // 196608
#define DBOFF  (SOFFB + 3584)        // d+bj row (512 f32)
#define BIG_SMEM (DBOFF + 2048)       // 202240
__global__ void __launch_bounds__(256) big_fused(const float* __restrict__ bout,
                                                 const float* __restrict__ bj,
                                                 const int* __restrict__ targets,
                                                 const int* __restrict__ in_lens,
                                                 const int* __restrict__ tgt_lens){
    int u    = blockIdx.x >> 3;          // 0..64
    int sub  = blockIdx.x & 7;
    int b    = sub >> 1;                 // 0..3
    int t0   = (sub & 1) * 128;
    if(u > tgt_lens[b]) return;          // dead column band
    if(t0 >= in_lens[b]) return;         // dead time band

    extern __shared__ char sm[];
    uint32_t sA = s2u(sm);
    uint32_t sB = sA + ABYTES;
    float* pm  = (float*)(sm + SOFFB);          // [2][128]
    float* ps  = pm + 256;                      // [2][128]
    float* pvt = ps + 256;                      // [2][128]
    float* pv0 = pvt + 256;                     // [128]
    float* db  = (float*)(sm + DBOFF);          // d_u + bj (512)

    int tid = threadIdx.x, wid = tid>>5, lane = tid&31;
    int g = lane>>2, tg = lane&3;
    int warp_m = wid & 3, warp_n = wid >> 2;    // 4 x 2
    int tgt = (u < Un) ? targets[b*Un + u] : -1;

    // ---- stage d_u + bj ----
    {
        const float* drow = g_d + (size_t)(b*U1+u)*Jn;
        #pragma unroll
        for(int i=0;i<2;i++){
            int k = tid + i*256;
            db[k] = drow[k] + bj[k];
        }
    }
    __syncthreads();

    // ---- prologue: H = tanh(e[bt] + db) -> bf16 into A smem; warp owns 16 rows ----
    {
        int r0 = wid*16;
        #pragma unroll
        for(int rr=0;rr<16;rr++){
            int r = r0 + rr;
            int bt = b*Tn + t0 + r;
            const float4* ep = (const float4*)(g_e + (size_t)bt*Jn);
            const float4* dp = (const float4*)db;
            uint32_t xr = XBITS(r);
            uint32_t colsw = (((uint32_t)(lane&7))*8u) ^ xr;
            #pragma unroll
            for(int i=0;i<4;i++){
                int k = i*128 + lane*4;
                float4 e4 = ep[k>>2], d4 = dp[k>>2];
                __nv_bfloat162 o0 = __floats2bfloat162_rn(tanhap(e4.x+d4.x), tanhap(e4.y+d4.y));
                __nv_bfloat162 o1 = __floats2bfloat162_rn(tanhap(e4.z+d4.z), tanhap(e4.w+d4.w));
                int kt = i*4 + (lane>>3);
                uint32_t addr = sA + (uint32_t)kt*8192 + (uint32_t)r*64 + colsw;
                uint32_t w0 = *(unsigned*)&o0, w1 = *(unsigned*)&o1;
                asm volatile("st.shared.v2.b32 [%0], {%1,%2};" :: "r"(addr), "r"(w0), "r"(w1));
            }
        }
    }

    // per-slot local rows (slot = mt*2 + half)
    int rows4[4];
    #pragma unroll
    for(int mt=0;mt<2;mt++)
        #pragma unroll
        for(int half=0;half<2;half++)
            rows4[mt*2+half] = warp_m*32 + mt*16 + half*8 + g;

    // ldmatrix swizzled offsets within a kt/buffer tile, both ks variants
    uint32_t aOff2[2][2];
    #pragma unroll
    for(int mt=0;mt<2;mt++){
        int r = warp_m*32 + mt*16 + (lane&7) + ((lane>>3)&1)*8;
        uint32_t off16 = ((lane>>4)&1)*16;
        #pragma unroll
        for(int ks=0;ks<2;ks++)
            aOff2[mt][ks] = (uint32_t)r*64 + ((off16 | (ks<<5)) ^ XBITS(r));
    }
    uint32_t bOff2[4][2];
    #pragma unroll
    for(int j=0;j<4;j++){
        int n = warp_n*64 + j*16 + (lane&7) + ((lane>>4)&1)*8;
        uint32_t off16 = ((lane>>3)&1)*16;
        #pragma unroll
        for(int ks=0;ks<2;ks++)
            bOff2[j][ks] = (uint32_t)n*64 + ((off16 | (ks<<5)) ^ XBITS(n));
    }

    float m4[4] = {-3.4e38f,-3.4e38f,-3.4e38f,-3.4e38f};
    float s4[4] = {0.f,0.f,0.f,0.f};
    float vt4[4] = {-3.4e38f,-3.4e38f,-3.4e38f,-3.4e38f};
    float v04[4] = {0.f,0.f,0.f,0.f};

    int brow = tid>>1, bc0 = (tid&1)*2;   // 128 rows x 2 x 16B per thread
    uint32_t bst0 = (uint32_t)brow*64 + (((uint32_t)bc0*16u)       ^ XBITS(brow));
    uint32_t bst1 = (uint32_t)brow*64 + (((uint32_t)bc0*16u + 16u) ^ XBITS(brow));
    #define LOADB(buf, stp) do{ \
        unsigned long long p = __cvta_generic_to_global( \
            (const char*)g_Wt + ((size_t)(((stp)>>4)*128 + brow))*1024 + ((stp)&15)*64 + bc0*16); \
        uint32_t dbase = sB + (uint32_t)(buf)*8192; \
        asm volatile("cp.async.cg.shared.global [%0], [%1], 16;" :: "r"(dbase + bst0), "l"(p)); \
        asm volatile("cp.async.cg.shared.global [%0], [%1], 16;" :: "r"(dbase + bst1), "l"(p+16)); \
    }while(0)

    // prefetch steps 0..3 (one commit group each)
    LOADB(0,0); asm volatile("cp.async.commit_group;");
    LOADB(1,1); asm volatile("cp.async.commit_group;");
    LOADB(2,2); asm volatile("cp.async.commit_group;");
    LOADB(3,3); asm volatile("cp.async.commit_group;");

    float acc[2][8][4];
    #pragma unroll
    for(int mt=0;mt<2;mt++)
        #pragma unroll
        for(int nt=0;nt<8;nt++)
            #pragma unroll
            for(int c=0;c<4;c++) acc[mt][nt][c]=0.f;

    for(int it=0; it<64; it++){
        int p0 = 2*it;
        if(p0+4 < 128){ LOADB((p0+4)&7, p0+4); }
        asm volatile("cp.async.commit_group;");
        if(p0+5 < 128){ LOADB((p0+5)&7, p0+5); }
        asm volatile("cp.async.commit_group;");
        asm volatile("cp.async.wait_group 4;");
        __syncthreads();

        #pragma unroll
        for(int half2=0; half2<2; half2++){
            int stp = p0 + half2;
            uint32_t aoff = sA + (uint32_t)(stp & 15)*8192;
            uint32_t boff = sB + (uint32_t)(stp & 7)*8192;
            #pragma unroll
            for(int ks=0;ks<2;ks++){
                uint32_t af[2][4];
                #pragma unroll
                for(int mt=0;mt<2;mt++)
                    asm volatile("ldmatrix.sync.aligned.m8n8.x4.shared.b16 {%0,%1,%2,%3}, [%4];"
                        : "=r"(af[mt][0]),"=r"(af[mt][1]),"=r"(af[mt][2]),"=r"(af[mt][3])
                        : "r"(aoff + aOff2[mt][ks]));
                uint32_t bf[8][2];
                #pragma unroll
                for(int j=0;j<4;j++){
                    uint32_t b0,b1,b2,b3;
                    asm volatile("ldmatrix.sync.aligned.m8n8.x4.shared.b16 {%0,%1,%2,%3}, [%4];"
                        : "=r"(b0),"=r"(b1),"=r"(b2),"=r"(b3)
                        : "r"(boff + bOff2[j][ks]));
                    bf[2*j][0]=b0; bf[2*j][1]=b1; bf[2*j+1][0]=b2; bf[2*j+1][1]=b3;
                }
                #pragma unroll
                for(int mt=0;mt<2;mt++)
                    #pragma unroll
                    for(int nt=0;nt<8;nt++)
                        asm volatile(
                            "mma.sync.aligned.m16n8k16.row.col.f32.bf16.bf16.f32 "
                            "{%0,%1,%2,%3}, {%4,%5,%6,%7}, {%8,%9}, {%0,%1,%2,%3};"
                            : "+f"(acc[mt][nt][0]), "+f"(acc[mt][nt][1]),
                              "+f"(acc[mt][nt][2]), "+f"(acc[mt][nt][3])
                            : "r"(af[mt][0]),"r"(af[mt][1]),"r"(af[mt][2]),"r"(af[mt][3]),
                              "r"(bf[nt][0]),"r"(bf[nt][1]));
            }
        }

        if(((p0+1) & 15) == 15){
            int nch = (p0+1) >> 4;
            int colw = nch*128 + warp_n*64;
            float br0[8], br1[8];
            #pragma unroll
            for(int nt=0;nt<8;nt++){
                br0[nt] = __ldg(&bout[colw + nt*8 + tg*2]);
                br1[nt] = __ldg(&bout[colw + nt*8 + tg*2 + 1]);
            }
            #pragma unroll
            for(int mt=0;mt<2;mt++){
                #pragma unroll
                for(int half=0;half<2;half++){
                    int slot = mt*2+half;
                    float v[16];
                    float cm = -3.4e38f;
                    #pragma unroll
                    for(int nt=0;nt<8;nt++){
                        v[nt*2]   = acc[mt][nt][half*2]   + br0[nt];
                        v[nt*2+1] = acc[mt][nt][half*2+1] + br1[nt];
                        cm = fmaxf(cm, fmaxf(v[nt*2], v[nt*2+1]));
                    }
                    float nm = fmaxf(m4[slot], cm);
                    float s = s4[slot]*__expf(m4[slot]-nm);
                    #pragma unroll
                    for(int nt=0;nt<8;nt++){
                        s += __expf(v[nt*2]-nm);
                        s += __expf(v[nt*2+1]-nm);
                        int c0 = colw + nt*8 + tg*2;
                        if(c0   == tgt) vt4[slot] = v[nt*2];
                        if(c0+1 == tgt) vt4[slot] = v[nt*2+1];
                    }
                    m4[slot] = nm; s4[slot] = s;
                    if(nch==0 && warp_n==0 && tg==0) v04[slot] = v[0];
                }
            }
            #pragma unroll
            for(int mt=0;mt<2;mt++)
                #pragma unroll
                for(int nt=0;nt<8;nt++)
                    #pragma unroll
                    for(int c=0;c<4;c++) acc[mt][nt][c]=0.f;
        }
    }
    #undef LOADB

    // ---- cross-quad + cross-warp_n combine ----
    #pragma unroll
    for(int slot=0;slot<4;slot++){
        #pragma unroll
        for(int o=1;o<4;o<<=1){
            float om = __shfl_xor_sync(0xffffffffu, m4[slot], o);
            float os = __shfl_xor_sync(0xffffffffu, s4[slot], o);
            float ov = __shfl_xor_sync(0xffffffffu, vt4[slot], o);
            float nm = fmaxf(m4[slot], om);
            s4[slot] = s4[slot]*__expf(m4[slot]-nm) + os*__expf(om-nm);
            m4[slot] = nm;
            vt4[slot] = fmaxf(vt4[slot], ov);
        }
        if(tg==0){
            int rl = rows4[slot];
            pm [warp_n*128 + rl] = m4[slot];
            ps [warp_n*128 + rl] = s4[slot];
            pvt[warp_n*128 + rl] = vt4[slot];
            if(warp_n==0) pv0[rl] = v04[slot];
        }
    }
    __syncthreads();
    if(tid < 128){
        int r = tid;
        int t = t0 + r;
        float m0 = pm[r], m1 = pm[128+r];
        float nm = fmaxf(m0, m1);
        float s = ps[r]*__expf(m0-nm) + ps[128+r]*__expf(m1-nm);
        float lse = nm + logf(s);
        g_blank[b*(Tn*U1) + t*U1 + u] = pv0[r] - lse;
        if(u < Un && u < tgt_lens[b]){
            float vt = fmaxf(pvt[r], pvt[128+r]);
            g_lbl[b*(Tn*Un) + t*Un + u] = vt - lse;
        }
    }
}

// ---------------- RNN-T forward DP: wavefront over SMEM-resident tables ----------------
#define DP_SMEM ((Tn*U1 + Tn*Un)*4)   // 132096 bytes
__global__ void dp_kernel(const int* __restrict__ in_lens, const int* __restrict__ tgt_lens,
                          float* __restrict__ out){
    extern __shared__ float smf[];
    float* s_blank = smf;              // Tn*U1
    float* s_lbl   = smf + Tn*U1;      // Tn*Un
    int b = blockIdx.x;
    for(int i=threadIdx.x;i<Tn*U1;i+=blockDim.x) s_blank[i] = g_blank[b*Tn*U1 + i];
    for(int i=threadIdx.x;i<Tn*Un;i+=blockDim.x) s_lbl[i]   = g_lbl[b*Tn*Un + i];
    __shared__ float buf[2][U1];
    __shared__ float fin;
    __syncthreads();
    int u = threadIdx.x;
    int tl = in_lens[b]-1;
    int uf = tgt_lens[b];
    int lim = tl + uf;
    for(int n=0;n<=lim;n++){
        float* cur = buf[n&1];
        const float* prev = buf[(n&1)^1];
        if(u <= Un){
            int t = n - u;
            if(t >= 0 && t < Tn){
                float val;
                if(t==0 && u==0)      val = 0.f;
                else if(t==0)         val = (u<=uf) ? prev[u-1] + s_lbl[u-1] : NEGF;
                else if(u==0)         val = prev[0]   + s_blank[(t-1)*U1];
                else if(u<=uf)        val = lae(prev[u]   + s_blank[(t-1)*U1 + u],
                                               prev[u-1] + s_lbl[t*Un + (u-1)]);
                else                  val = NEGF;
                cur[u] = val;
                if(t==tl && u==uf) fin = val + s_blank[t*U1 + u];
            }
        }
        __syncthreads();
    }
    if(threadIdx.x==0) atomicAdd(out, -fin * (1.0f/Bn));
}

// ---------------- launch ----------------
extern "C" void kernel_launch(void* const* d_in, const int* in_sizes, int n_in,
                              void* d_out, int out_size){
    (void)in_sizes; (void)n_in; (void)out_size;
    const float* inputs  = (const float*)d_in[0];
    const float* W_enc   = (const float*)d_in[1];
    const float* emb     = (const float*)d_in[2];
    const float* W_jenc  = (const float*)d_in[3];
    const float* W_jdec  = (const float*)d_in[4];
    const float* b_j     = (const float*)d_in[5];
    const float* W_out   = (const float*)d_in[6];
    const float* b_out   = (const float*)d_in[7];
    const int*   targets = (const int*)d_in[8];
    const int*   in_lens = (const int*)d_in[9];
    const int*   tgt_lens= (const int*)d_in[10];
    float* out = (float*)d_out;

    cudaFuncSetAttribute(big_fused, cudaFuncAttributeMaxDynamicSharedMemorySize, BIG_SMEM);
    cudaFuncSetAttribute(dp_kernel, cudaFuncAttributeMaxDynamicSharedMemorySize, DP_SMEM);

    void *p_wc, *p_e, *p_dec, *p_d;
    cudaGetSymbolAddress(&p_wc,  g_Wcomb);
    cudaGetSymbolAddress(&p_e,   g_e);
    cudaGetSymbolAddress(&p_dec, g_dec);
    cudaGetSymbolAddress(&p_d,   g_d);

    // W_comb = W_enc(80,512) @ W_jenc(512,512)
    gemm32<<<dim3(Jn/32, (Fn+31)/32), 256>>>(W_enc, W_jenc, (float*)p_wc, Fn, Jn, Hn);
    gather_dec<<<Bn*U1, 128>>>(emb, targets, out);
    wtrans<<<dim3(Vn/32, Jn/32), dim3(32,8)>>>(W_out);
    // e = inputs(1024,80) @ W_comb(80,512)
    gemm32<<<dim3(Jn/32, (Bn*Tn)/32), 256>>>(inputs, (const float*)p_wc, (float*)p_e, Bn*Tn, Jn, Fn);
    // d = dec(260,512) @ W_jdec(512,512)
    gemm32<<<dim3(Jn/32, (Bn*U1+31)/32), 256>>>((const float*)p_dec, W_jdec, (float*)p_d, Bn*U1, Jn, Hn);
    big_fused<<<U1*Bn*2, 256, BIG_SMEM>>>(b_out, b_j, targets, in_lens, tgt_lens);
    dp_kernel<<<Bn, 128, DP_SMEM>>>(in_lens, tgt_lens, out);
}

// round 13
// speedup vs baseline: 1.2255x; 1.0078x over previous
#include <cuda_runtime.h>
#include <cuda_bf16.h>
#include <math.h>
#include <cstdint>

// Problem constants
#define Bn 4
#define Tn 256
#define Un 64
#define U1 65
#define Vn 1024
#define Fn 80
#define Hn 512
#define Jn 512
#define NROWS (Bn*Tn*U1)   // 66560 = 520*128
#define NEGF (-1e30f)

// ---------------- scratch (static __device__, allocation-free) ----------------
__device__ float g_Wcomb[Fn*Jn];                 // W_enc @ W_jenc (80x512)
__device__ float g_e  [Bn*Tn*Jn];                // (1024, 512)
__device__ float g_dec[Bn*U1*Hn];                // (260, 512)
__device__ float g_d  [Bn*U1*Jn];                // (260, 512)
__device__ __nv_bfloat16 g_Wt[(size_t)Vn*Jn];    // W_out^T bf16, [V][J] K-major
__device__ float g_blank[NROWS];                 // [b][t][u]
__device__ float g_lbl[Bn*Tn*Un];                // [b][t][u]

__device__ __forceinline__ float lae(float a, float b){
    float m = fmaxf(a,b);
    return m + log1pf(__expf(fminf(a,b) - m));
}
__device__ __forceinline__ uint32_t s2u(const void* p){
    uint32_t a;
    asm("{ .reg .u64 t; cvta.to.shared.u64 t, %1; cvt.u32.u64 %0, t; }" : "=r"(a) : "l"(p));
    return a;
}
__device__ __forceinline__ float tanhap(float x){
    float y; asm("tanh.approx.f32 %0, %1;" : "=f"(y) : "f"(x)); return y;
}
// per-row swizzle bits for 64B rows: flips 16B-chunk index (bits 4,5) by row bits 1,2
#define XBITS(r) ((((uint32_t)(r))&6u)<<3)

// ---------------- 32x32-tile SGEMM body (device fn, 256 threads) ----------------
__device__ void gemm32_dev(const float* __restrict__ A, const float* __restrict__ B,
                           float* __restrict__ C, int M, int N, int K, int bx, int by,
                           float* As /*[32*33]*/, float* Bs /*[32*33]*/){
    int tid = threadIdx.x;
    int tx = tid & 15, ty = tid >> 4;
    int rowBase = by*32, colBase = bx*32;
    float acc[2][2] = {};
    for(int k0=0;k0<K;k0+=32){
        #pragma unroll
        for(int i=0;i<4;i++){
            int idx = i*256+tid;
            int m = idx>>5, k = idx&31;
            int gm = rowBase+m, gk = k0+k;
            As[m*33+k] = (gm<M && gk<K) ? A[(size_t)gm*K+gk] : 0.f;
            int kb = idx>>5, n = idx&31;
            int gkb = k0+kb, gn = colBase+n;
            Bs[kb*33+n] = (gkb<K && gn<N) ? B[(size_t)gkb*N+gn] : 0.f;
        }
        __syncthreads();
        #pragma unroll
        for(int kk=0;kk<32;kk++){
            float a0 = As[(ty*2+0)*33+kk], a1 = As[(ty*2+1)*33+kk];
            float b0 = Bs[kk*33+tx*2+0], b1 = Bs[kk*33+tx*2+1];
            acc[0][0] = fmaf(a0,b0,acc[0][0]);
            acc[0][1] = fmaf(a0,b1,acc[0][1]);
            acc[1][0] = fmaf(a1,b0,acc[1][0]);
            acc[1][1] = fmaf(a1,b1,acc[1][1]);
        }
        __syncthreads();
    }
    #pragma unroll
    for(int i=0;i<2;i++){
        int gm = rowBase+ty*2+i;
        if(gm<M)
            #pragma unroll
            for(int j=0;j<2;j++){
                int gn = colBase+tx*2+j;
                if(gn<N) C[(size_t)gm*N+gn]=acc[i][j];
            }
    }
}

// ---------------- prep1: Wcomb GEMM + gather_dec + wtrans in one launch ----------------
// blockIdx [0,48): Wcomb = W_enc(80,512) @ W_jenc(512,512)  (3 row x 16 col tiles)
// blockIdx [48,308): gather decoder embedding row (row = bid-48); bid==48 zeroes out
// blockIdx [308,820): W_out transpose tile -> g_Wt bf16
__global__ __launch_bounds__(256) void prep1(const float* __restrict__ W_enc,
                                             const float* __restrict__ W_jenc,
                                             const float* __restrict__ emb,
                                             const int* __restrict__ targets,
                                             const float* __restrict__ W_out,
                                             float* __restrict__ out){
    __shared__ float sh[2*32*33];
    int bid = blockIdx.x, tid = threadIdx.x;
    if(bid < 48){
        gemm32_dev(W_enc, W_jenc, g_Wcomb, Fn, Jn, Hn, bid&15, bid>>4, sh, sh+32*33);
    } else if(bid < 308){
        if(bid==48 && tid==0) out[0] = 0.f;
        int row = bid - 48;                 // 0..259 = b*65+u
        int b = row / U1, u = row - b*U1;
        int tok = (u==0) ? 0 : targets[b*Un + (u-1)];
        const float* src = emb + (size_t)tok*Hn;
        float* dst = g_dec + (size_t)row*Hn;
        #pragma unroll
        for(int i=0;i<2;i++) dst[tid + i*256] = src[tid + i*256];
    } else {
        int idx = bid - 308;                // 512 tiles: 32 v-tiles x 16 j-tiles
        int v0 = (idx & 31)*32, j0 = (idx >> 5)*32;
        float (*t)[33] = (float(*)[33])sh;
        int tx = tid & 31, ty = tid >> 5;   // 32 x 8
        for(int i=ty;i<32;i+=8)
            t[i][tx] = W_out[(size_t)(j0+i)*Vn + v0 + tx];
        __syncthreads();
        for(int i=ty;i<32;i+=8)
            g_Wt[(size_t)(v0+i)*Jn + j0 + tx] = __float2bfloat16(t[tx][i]);
    }
}

// ---------------- prep2: e-GEMM + d-GEMM in one launch ----------------
// blockIdx [0,512): e = inputs(1024,80) @ Wcomb(80,512)
// blockIdx [512,656): d = dec(260,512) @ W_jdec(512,512)
__global__ __launch_bounds__(256) void prep2(const float* __restrict__ inputs,
                                             const float* __restrict__ W_jdec){
    __shared__ float sh[2*32*33];
    int bid = blockIdx.x;
    if(bid < 512){
        gemm32_dev(inputs, g_Wcomb, g_e, Bn*Tn, Jn, Fn, bid&15, bid>>4, sh, sh+32*33);
    } else {
        int idx = bid - 512;                // 144: 9 row x 16 col tiles
        gemm32_dev(g_dec, W_jdec, g_d, Bn*U1, Jn, Hn, idx&15, idx>>4, sh, sh+32*33);
    }
}

// ================= fused joint kernel (u-major tiling + dead-CTA skip) =================
// Grid 520 = 65 u x 4 b x 2 t-halves. CTA: 128 t-rows (single u,b) x 1024 cols.
// Early exit if u > tgt_lens[b] or t0 >= in_lens[b]  (rows never read by DP).
// A full-K [16 kt][128 rows][64B swizzled] = 128KB; B 8-stage ring 8x8KB = 64KB.
// Swizzle: addr = base + row*64 + (off ^ XBITS(row)). 2 kt per barrier, dist 4.
#define ABYTES (16*128*64)            // 131072
#define BRING  (8*128*64)             // 65536
#define SOFFB  (ABYTES + BRING)       // 196608
#define DBOFF  (SOFFB + 3584)         // d+bj row (512 f32)
#define BIG_SMEM (DBOFF + 2048)       // 202240
__global__ void __launch_bounds__(256) big_fused(const float* __restrict__ bout,
                                                 const float* __restrict__ bj,
                                                 const int* __restrict__ targets,
                                                 const int* __restrict__ in_lens,
                                                 const int* __restrict__ tgt_lens){
    int u    = blockIdx.x >> 3;          // 0..64
    int sub  = blockIdx.x & 7;
    int b    = sub >> 1;                 // 0..3
    int t0   = (sub & 1) * 128;
    if(u > tgt_lens[b]) return;          // dead column band
    if(t0 >= in_lens[b]) return;         // dead time band

    extern __shared__ char sm[];
    uint32_t sA = s2u(sm);
    uint32_t sB = sA + ABYTES;
    float* pm  = (float*)(sm + SOFFB);          // [2][128]
    float* ps  = pm + 256;                      // [2][128]
    float* pvt = ps + 256;                      // [2][128]
    float* pv0 = pvt + 256;                     // [128]
    float* db  = (float*)(sm + DBOFF);          // d_u + bj (512)

    int tid = threadIdx.x, wid = tid>>5, lane = tid&31;
    int g = lane>>2, tg = lane&3;
    int warp_m = wid & 3, warp_n = wid >> 2;    // 4 x 2
    int tgt = (u < Un) ? targets[b*Un + u] : -1;

    // ---- stage d_u + bj ----
    {
        const float* drow = g_d + (size_t)(b*U1+u)*Jn;
        #pragma unroll
        for(int i=0;i<2;i++){
            int k = tid + i*256;
            db[k] = drow[k] + bj[k];
        }
    }
    __syncthreads();

    // ---- prologue: H = tanh(e[bt] + db) -> bf16 into A smem; warp owns 16 rows ----
    {
        int r0 = wid*16;
        #pragma unroll
        for(int rr=0;rr<16;rr++){
            int r = r0 + rr;
            int bt = b*Tn + t0 + r;
            const float4* ep = (const float4*)(g_e + (size_t)bt*Jn);
            const float4* dp = (const float4*)db;
            uint32_t xr = XBITS(r);
            uint32_t colsw = (((uint32_t)(lane&7))*8u) ^ xr;
            #pragma unroll
            for(int i=0;i<4;i++){
                int k = i*128 + lane*4;
                float4 e4 = ep[k>>2], d4 = dp[k>>2];
                __nv_bfloat162 o0 = __floats2bfloat162_rn(tanhap(e4.x+d4.x), tanhap(e4.y+d4.y));
                __nv_bfloat162 o1 = __floats2bfloat162_rn(tanhap(e4.z+d4.z), tanhap(e4.w+d4.w));
                int kt = i*4 + (lane>>3);
                uint32_t addr = sA + (uint32_t)kt*8192 + (uint32_t)r*64 + colsw;
                uint32_t w0 = *(unsigned*)&o0, w1 = *(unsigned*)&o1;
                asm volatile("st.shared.v2.b32 [%0], {%1,%2};" :: "r"(addr), "r"(w0), "r"(w1));
            }
        }
    }

    // per-slot local rows (slot = mt*2 + half)
    int rows4[4];
    #pragma unroll
    for(int mt=0;mt<2;mt++)
        #pragma unroll
        for(int half=0;half<2;half++)
            rows4[mt*2+half] = warp_m*32 + mt*16 + half*8 + g;

    // ldmatrix swizzled offsets within a kt/buffer tile, both ks variants
    uint32_t aOff2[2][2];
    #pragma unroll
    for(int mt=0;mt<2;mt++){
        int r = warp_m*32 + mt*16 + (lane&7) + ((lane>>3)&1)*8;
        uint32_t off16 = ((lane>>4)&1)*16;
        #pragma unroll
        for(int ks=0;ks<2;ks++)
            aOff2[mt][ks] = (uint32_t)r*64 + ((off16 | (ks<<5)) ^ XBITS(r));
    }
    uint32_t bOff2[4][2];
    #pragma unroll
    for(int j=0;j<4;j++){
        int n = warp_n*64 + j*16 + (lane&7) + ((lane>>4)&1)*8;
        uint32_t off16 = ((lane>>3)&1)*16;
        #pragma unroll
        for(int ks=0;ks<2;ks++)
            bOff2[j][ks] = (uint32_t)n*64 + ((off16 | (ks<<5)) ^ XBITS(n));
    }

    float m4[4] = {-3.4e38f,-3.4e38f,-3.4e38f,-3.4e38f};
    float s4[4] = {0.f,0.f,0.f,0.f};
    float vt4[4] = {-3.4e38f,-3.4e38f,-3.4e38f,-3.4e38f};
    float v04[4] = {0.f,0.f,0.f,0.f};

    int brow = tid>>1, bc0 = (tid&1)*2;   // 128 rows x 2 x 16B per thread
    uint32_t bst0 = (uint32_t)brow*64 + (((uint32_t)bc0*16u)       ^ XBITS(brow));
    uint32_t bst1 = (uint32_t)brow*64 + (((uint32_t)bc0*16u + 16u) ^ XBITS(brow));
    #define LOADB(buf, stp) do{ \
        unsigned long long p = __cvta_generic_to_global( \
            (const char*)g_Wt + ((size_t)(((stp)>>4)*128 + brow))*1024 + ((stp)&15)*64 + bc0*16); \
        uint32_t dbase = sB + (uint32_t)(buf)*8192; \
        asm volatile("cp.async.cg.shared.global [%0], [%1], 16;" :: "r"(dbase + bst0), "l"(p)); \
        asm volatile("cp.async.cg.shared.global [%0], [%1], 16;" :: "r"(dbase + bst1), "l"(p+16)); \
    }while(0)

    // prefetch steps 0..3 (one commit group each)
    LOADB(0,0); asm volatile("cp.async.commit_group;");
    LOADB(1,1); asm volatile("cp.async.commit_group;");
    LOADB(2,2); asm volatile("cp.async.commit_group;");
    LOADB(3,3); asm volatile("cp.async.commit_group;");

    float acc[2][8][4];
    #pragma unroll
    for(int mt=0;mt<2;mt++)
        #pragma unroll
        for(int nt=0;nt<8;nt++)
            #pragma unroll
            for(int c=0;c<4;c++) acc[mt][nt][c]=0.f;

    for(int it=0; it<64; it++){
        int p0 = 2*it;
        if(p0+4 < 128){ LOADB((p0+4)&7, p0+4); }
        asm volatile("cp.async.commit_group;");
        if(p0+5 < 128){ LOADB((p0+5)&7, p0+5); }
        asm volatile("cp.async.commit_group;");
        asm volatile("cp.async.wait_group 4;");
        __syncthreads();

        #pragma unroll
        for(int half2=0; half2<2; half2++){
            int stp = p0 + half2;
            uint32_t aoff = sA + (uint32_t)(stp & 15)*8192;
            uint32_t boff = sB + (uint32_t)(stp & 7)*8192;
            #pragma unroll
            for(int ks=0;ks<2;ks++){
                uint32_t af[2][4];
                #pragma unroll
                for(int mt=0;mt<2;mt++)
                    asm volatile("ldmatrix.sync.aligned.m8n8.x4.shared.b16 {%0,%1,%2,%3}, [%4];"
                        : "=r"(af[mt][0]),"=r"(af[mt][1]),"=r"(af[mt][2]),"=r"(af[mt][3])
                        : "r"(aoff + aOff2[mt][ks]));
                uint32_t bf[8][2];
                #pragma unroll
                for(int j=0;j<4;j++){
                    uint32_t b0,b1,b2,b3;
                    asm volatile("ldmatrix.sync.aligned.m8n8.x4.shared.b16 {%0,%1,%2,%3}, [%4];"
                        : "=r"(b0),"=r"(b1),"=r"(b2),"=r"(b3)
                        : "r"(boff + bOff2[j][ks]));
                    bf[2*j][0]=b0; bf[2*j][1]=b1; bf[2*j+1][0]=b2; bf[2*j+1][1]=b3;
                }
                #pragma unroll
                for(int mt=0;mt<2;mt++)
                    #pragma unroll
                    for(int nt=0;nt<8;nt++)
                        asm volatile(
                            "mma.sync.aligned.m16n8k16.row.col.f32.bf16.bf16.f32 "
                            "{%0,%1,%2,%3}, {%4,%5,%6,%7}, {%8,%9}, {%0,%1,%2,%3};"
                            : "+f"(acc[mt][nt][0]), "+f"(acc[mt][nt][1]),
                              "+f"(acc[mt][nt][2]), "+f"(acc[mt][nt][3])
                            : "r"(af[mt][0]),"r"(af[mt][1]),"r"(af[mt][2]),"r"(af[mt][3]),
                              "r"(bf[nt][0]),"r"(bf[nt][1]));
            }
        }

        if(((p0+1) & 15) == 15){
            int nch = (p0+1) >> 4;
            int colw = nch*128 + warp_n*64;
            float br0[8], br1[8];
            #pragma unroll
            for(int nt=0;nt<8;nt++){
                br0[nt] = __ldg(&bout[colw + nt*8 + tg*2]);
                br1[nt] = __ldg(&bout[colw + nt*8 + tg*2 + 1]);
            }
            #pragma unroll
            for(int mt=0;mt<2;mt++){
                #pragma unroll
                for(int half=0;half<2;half++){
                    int slot = mt*2+half;
                    float v[16];
                    float cm = -3.4e38f;
                    #pragma unroll
                    for(int nt=0;nt<8;nt++){
                        v[nt*2]   = acc[mt][nt][half*2]   + br0[nt];
                        v[nt*2+1] = acc[mt][nt][half*2+1] + br1[nt];
                        cm = fmaxf(cm, fmaxf(v[nt*2], v[nt*2+1]));
                    }
                    float nm = fmaxf(m4[slot], cm);
                    float s = s4[slot]*__expf(m4[slot]-nm);
                    #pragma unroll
                    for(int nt=0;nt<8;nt++){
                        s += __expf(v[nt*2]-nm);
                        s += __expf(v[nt*2+1]-nm);
                        int c0 = colw + nt*8 + tg*2;
                        if(c0   == tgt) vt4[slot] = v[nt*2];
                        if(c0+1 == tgt) vt4[slot] = v[nt*2+1];
                    }
                    m4[slot] = nm; s4[slot] = s;
                    if(nch==0 && warp_n==0 && tg==0) v04[slot] = v[0];
                }
            }
            #pragma unroll
            for(int mt=0;mt<2;mt++)
                #pragma unroll
                for(int nt=0;nt<8;nt++)
                    #pragma unroll
                    for(int c=0;c<4;c++) acc[mt][nt][c]=0.f;
        }
    }
    #undef LOADB

    // ---- cross-quad + cross-warp_n combine ----
    #pragma unroll
    for(int slot=0;slot<4;slot++){
        #pragma unroll
        for(int o=1;o<4;o<<=1){
            float om = __shfl_xor_sync(0xffffffffu, m4[slot], o);
            float os = __shfl_xor_sync(0xffffffffu, s4[slot], o);
            float ov = __shfl_xor_sync(0xffffffffu, vt4[slot], o);
            float nm = fmaxf(m4[slot], om);
            s4[slot] = s4[slot]*__expf(m4[slot]-nm) + os*__expf(om-nm);
            m4[slot] = nm;
            vt4[slot] = fmaxf(vt4[slot], ov);
        }
        if(tg==0){
            int rl = rows4[slot];
            pm [warp_n*128 + rl] = m4[slot];
            ps [warp_n*128 + rl] = s4[slot];
            pvt[warp_n*128 + rl] = vt4[slot];
            if(warp_n==0) pv0[rl] = v04[slot];
        }
    }
    __syncthreads();
    if(tid < 128){
        int r = tid;
        int t = t0 + r;
        float m0 = pm[r], m1 = pm[128+r];
        float nm = fmaxf(m0, m1);
        float s = ps[r]*__expf(m0-nm) + ps[128+r]*__expf(m1-nm);
        float lse = nm + logf(s);
        g_blank[b*(Tn*U1) + t*U1 + u] = pv0[r] - lse;
        if(u < Un && u < tgt_lens[b]){
            float vt = fmaxf(pvt[r], pvt[128+r]);
            g_lbl[b*(Tn*Un) + t*Un + u] = vt - lse;
        }
    }
}

// ---------------- RNN-T forward DP: wavefront over SMEM-resident tables ----------------
#define DP_SMEM ((Tn*U1 + Tn*Un)*4)   // 132096 bytes
__global__ void dp_kernel(const int* __restrict__ in_lens, const int* __restrict__ tgt_lens,
                          float* __restrict__ out){
    extern __shared__ float smf[];
    float* s_blank = smf;              // Tn*U1
    float* s_lbl   = smf + Tn*U1;      // Tn*Un
    int b = blockIdx.x;
    for(int i=threadIdx.x;i<Tn*U1;i+=blockDim.x) s_blank[i] = g_blank[b*Tn*U1 + i];
    for(int i=threadIdx.x;i<Tn*Un;i+=blockDim.x) s_lbl[i]   = g_lbl[b*Tn*Un + i];
    __shared__ float buf[2][U1];
    __shared__ float fin;
    __syncthreads();
    int u = threadIdx.x;
    int tl = in_lens[b]-1;
    int uf = tgt_lens[b];
    int lim = tl + uf;
    for(int n=0;n<=lim;n++){
        float* cur = buf[n&1];
        const float* prev = buf[(n&1)^1];
        if(u <= Un){
            int t = n - u;
            if(t >= 0 && t < Tn){
                float val;
                if(t==0 && u==0)      val = 0.f;
                else if(t==0)         val = (u<=uf) ? prev[u-1] + s_lbl[u-1] : NEGF;
                else if(u==0)         val = prev[0]   + s_blank[(t-1)*U1];
                else if(u<=uf)        val = lae(prev[u]   + s_blank[(t-1)*U1 + u],
                                               prev[u-1] + s_lbl[t*Un + (u-1)]);
                else                  val = NEGF;
                cur[u] = val;
                if(t==tl && u==uf) fin = val + s_blank[t*U1 + u];
            }
        }
        __syncthreads();
    }
    if(threadIdx.x==0) atomicAdd(out, -fin * (1.0f/Bn));
}

// ---------------- launch ----------------
extern "C" void kernel_launch(void* const* d_in, const int* in_sizes, int n_in,
                              void* d_out, int out_size){
    (void)in_sizes; (void)n_in; (void)out_size;
    const float* inputs  = (const float*)d_in[0];
    const float* W_enc   = (const float*)d_in[1];
    const float* emb     = (const float*)d_in[2];
    const float* W_jenc  = (const float*)d_in[3];
    const float* W_jdec  = (const float*)d_in[4];
    const float* b_j     = (const float*)d_in[5];
    const float* W_out   = (const float*)d_in[6];
    const float* b_out   = (const float*)d_in[7];
    const int*   targets = (const int*)d_in[8];
    const int*   in_lens = (const int*)d_in[9];
    const int*   tgt_lens= (const int*)d_in[10];
    float* out = (float*)d_out;

    cudaFuncSetAttribute(big_fused, cudaFuncAttributeMaxDynamicSharedMemorySize, BIG_SMEM);
    cudaFuncSetAttribute(dp_kernel, cudaFuncAttributeMaxDynamicSharedMemorySize, DP_SMEM);

    prep1<<<820, 256>>>(W_enc, W_jenc, emb, targets, W_out, out);
    prep2<<<656, 256>>>(inputs, W_jdec);
    big_fused<<<U1*Bn*2, 256, BIG_SMEM>>>(b_out, b_j, targets, in_lens, tgt_lens);
    dp_kernel<<<Bn, 128, DP_SMEM>>>(in_lens, tgt_lens, out);
}